// round 4
// baseline (speedup 1.0000x reference)
#include <cuda_runtime.h>
#include <cstdint>

// Problem constants (fixed by the reference)
#define N_TOKENS  131072
#define HIDDEN    2048
#define N_RANKS   8
#define N_EXPERTS 16
#define NSEG (N_RANKS * N_EXPERTS)   // 128
#define VEC_PER_ROW (HIDDEN / 4)     // 512 float4

// d_out float layout:
//   [0, N_TOKENS*HIDDEN)   permute_tokens
//   [+N_TOKENS)            permute_per_token_scales
//   [+N_TOKENS)            idx (as float, exact: < 2^24)
//   [+N_EXPERTS)           expert_token_num (as float)
#define OFF_SCALES ((size_t)N_TOKENS * HIDDEN)
#define OFF_IDX    (OFF_SCALES + N_TOKENS)
#define OFF_ETN    (OFF_IDX + N_TOKENS)

#define GRID_BLOCKS (148 * 8)   // persistent: 8 CTAs/SM x 148 SMs

// ---------------------------------------------------------------------------
// Single fused persistent kernel.
//  - Each block builds the segment offset tables once (smem), then
//    grid-strides over output rows: binary-search the segment, copy the
//    8 KB row (2 x float4 per thread), and write scale + idx inline.
//  - Block 0 additionally writes expert_token_num.
// ---------------------------------------------------------------------------
__global__ void __launch_bounds__(256, 8)
k_fused(const float4* __restrict__ tokens,
        const int*    __restrict__ counts,
        const float*  __restrict__ scales,
        float*        __restrict__ out) {
    __shared__ int s_counts[NSEG];
    __shared__ int s_in_start[NSEG];
    __shared__ int s_out_start[NSEG + 1];

    const int t = threadIdx.x;
    float4* __restrict__ out4 = (float4*)out;   // token region, float4 view

    if (t < NSEG) s_counts[t] = __ldg(&counts[t]);
    __syncthreads();

    if (t == 0) {
        // input prefix: flat order s = r*E + e (natural order of counts)
        int acc = 0;
        #pragma unroll 4
        for (int s = 0; s < NSEG; ++s) { s_in_start[s] = acc; acc += s_counts[s]; }
        // output prefix: expert-major order s = e*R + r
        acc = 0;
        #pragma unroll 4
        for (int s = 0; s < NSEG; ++s) {
            int e = s >> 3;             // s / N_RANKS
            int r = s & 7;              // s % N_RANKS
            s_out_start[s] = acc;
            acc += s_counts[r * N_EXPERTS + e];
        }
        s_out_start[NSEG] = acc;
    }
    // expert_token_num[e] = sum_r counts[r][e]  (block 0 only)
    if (blockIdx.x == 0 && t < N_EXPERTS) {
        int sum = 0;
        #pragma unroll
        for (int r = 0; r < N_RANKS; ++r) sum += __ldg(&counts[r * N_EXPERTS + t]);
        out[OFF_ETN + t] = (float)sum;
    }
    __syncthreads();

    // Grid-stride over output rows.
    for (int row = blockIdx.x; row < N_TOKENS; row += GRID_BLOCKS) {
        // binary search: largest s with out_start[s] <= row  (7 steps, smem
        // broadcast — every lane reads the same address)
        int lo = 0, hi = NSEG;
        #pragma unroll 7
        while (hi - lo > 1) {
            int mid = (lo + hi) >> 1;
            if (s_out_start[mid] <= row) lo = mid; else hi = mid;
        }
        const int e = lo >> 3;
        const int r = lo & 7;
        const int src = s_in_start[r * N_EXPERTS + e] + (row - s_out_start[lo]);

        const float4* __restrict__ in = tokens + (size_t)src * VEC_PER_ROW;
        float4*       __restrict__ o  = out4   + (size_t)row * VEC_PER_ROW;

        // 8 KB row copy: 256 threads x 2 float4. Read-once -> streaming loads.
        float4 a = __ldcs(&in[t]);
        float4 b = __ldcs(&in[t + 256]);

        if (t == 0) {
            out[OFF_SCALES + row] = __ldg(&scales[src]);
            out[OFF_IDX + row]    = (float)src;
        }

        o[t]       = a;
        o[t + 256] = b;
    }
}

// ---------------------------------------------------------------------------
extern "C" void kernel_launch(void* const* d_in, const int* in_sizes, int n_in,
                              void* d_out, int out_size) {
    const float* tokens = (const float*)d_in[0];
    const int*   counts = (const int*)d_in[1];     // [N_RANKS, N_EXPERTS]
    const float* scales = (const float*)d_in[2];
    // d_in[3] = expert_token_num_type (1), d_in[4] = idx_type (0) — fixed.
    float* out = (float*)d_out;

    k_fused<<<GRID_BLOCKS, 256>>>((const float4*)tokens, counts, scales, out);
}

// round 5
// speedup vs baseline: 1.1552x; 1.1552x over previous
#include <cuda_runtime.h>
#include <cstdint>

// Problem constants (fixed by the reference)
#define N_TOKENS  131072
#define HIDDEN    2048
#define N_RANKS   8
#define N_EXPERTS 16
#define NSEG (N_RANKS * N_EXPERTS)   // 128
#define VEC_PER_ROW (HIDDEN / 4)     // 512 float4

// Scratch (no cudaMalloc allowed)
__device__ int g_src_row[N_TOKENS];   // source row for each output row

// d_out float layout:
//   [0, N_TOKENS*HIDDEN)   permute_tokens
//   [+N_TOKENS)            permute_per_token_scales
//   [+N_TOKENS)            idx (as float, exact: < 2^24)
//   [+N_EXPERTS)           expert_token_num (as float)
#define OFF_SCALES ((size_t)N_TOKENS * HIDDEN)
#define OFF_IDX    (OFF_SCALES + N_TOKENS)
#define OFF_ETN    (OFF_IDX + N_TOKENS)

// ---------------------------------------------------------------------------
// Kernel 1: fused setup + index. 512 blocks x 256 threads; each thread owns
// exactly one token. Each block rebuilds the two 128-entry prefix tables with
// a 7-step Hillis-Steele scan (cheap, fully parallel, no cross-block dep).
// ---------------------------------------------------------------------------
__global__ void __launch_bounds__(256)
k_index(const int* __restrict__ counts, const float* __restrict__ scales,
        float* __restrict__ out) {
    __shared__ int sa[NSEG];          // inclusive scan, input order  (r*E + e)
    __shared__ int sb[NSEG];          // inclusive scan, output order (e*R + r)
    __shared__ int s_in_start[NSEG];
    __shared__ int s_out_start[NSEG + 1];

    const int t = threadIdx.x;

    int own_a = 0, own_b = 0;
    if (t < NSEG) {
        own_a = __ldg(&counts[t]);                                    // flat r*E+e
        own_b = __ldg(&counts[(t & 7) * N_EXPERTS + (t >> 3)]);       // seg e*R+r
        sa[t] = own_a;
        sb[t] = own_b;
    }
    __syncthreads();

    // Hillis-Steele inclusive scan over both tables, 7 steps.
    #pragma unroll
    for (int off = 1; off < NSEG; off <<= 1) {
        int va = 0, vb = 0;
        if (t < NSEG && t >= off) { va = sa[t - off]; vb = sb[t - off]; }
        __syncthreads();
        if (t < NSEG && t >= off) { sa[t] += va; sb[t] += vb; }
        __syncthreads();
    }

    if (t < NSEG) {
        s_in_start[t]  = sa[t] - own_a;   // exclusive
        s_out_start[t] = sb[t] - own_b;
    }
    if (t == 0) s_out_start[NSEG] = N_TOKENS;

    // expert_token_num[e] = sum_r counts[r][e]  (block 0 only)
    if (blockIdx.x == 0 && t < N_EXPERTS) {
        int sum = 0;
        #pragma unroll
        for (int r = 0; r < N_RANKS; ++r) sum += __ldg(&counts[r * N_EXPERTS + t]);
        out[OFF_ETN + t] = (float)sum;
    }
    __syncthreads();

    const int i = blockIdx.x * 256 + t;   // one token per thread, grid = 512

    // binary search: largest s with out_start[s] <= i  (7 steps)
    int lo = 0, hi = NSEG;
    #pragma unroll 7
    while (hi - lo > 1) {
        int mid = (lo + hi) >> 1;
        if (s_out_start[mid] <= i) lo = mid; else hi = mid;
    }
    const int e = lo >> 3;                // lo / N_RANKS
    const int r = lo & 7;                 // lo % N_RANKS
    const int src = s_in_start[r * N_EXPERTS + e] + (i - s_out_start[lo]);

    g_src_row[i]        = src;
    out[OFF_SCALES + i] = __ldg(&scales[src]);
    out[OFF_IDX + i]    = (float)src;
}

// ---------------------------------------------------------------------------
// Kernel 2: the big gather copy — exact R2 structure (proven 311.8us total).
// One block per output row, 256 threads x 2 float4 = 8 KB, fully coalesced.
// ---------------------------------------------------------------------------
__global__ void __launch_bounds__(256, 8) k_copy(const float4* __restrict__ tokens,
                                                 float4* __restrict__ out) {
    int row = blockIdx.x;
    int src = __ldg(&g_src_row[row]);   // same addr all threads: broadcast

    const float4* __restrict__ in = tokens + (size_t)src * VEC_PER_ROW;
    float4* __restrict__ o        = out    + (size_t)row * VEC_PER_ROW;

    int t = threadIdx.x;
    float4 a = __ldg(&in[t]);
    float4 b = __ldg(&in[t + 256]);
    o[t]       = a;
    o[t + 256] = b;
}

// ---------------------------------------------------------------------------
extern "C" void kernel_launch(void* const* d_in, const int* in_sizes, int n_in,
                              void* d_out, int out_size) {
    const float* tokens = (const float*)d_in[0];
    const int*   counts = (const int*)d_in[1];     // [N_RANKS, N_EXPERTS]
    const float* scales = (const float*)d_in[2];
    // d_in[3] = expert_token_num_type (1), d_in[4] = idx_type (0) — fixed.
    float* out = (float*)d_out;

    k_index<<<N_TOKENS / 256, 256>>>(counts, scales, out);
    k_copy<<<N_TOKENS, 256>>>((const float4*)tokens, (float4*)out);
}